// round 15
// baseline (speedup 1.0000x reference)
#include <cuda_runtime.h>
#include <cuda_fp16.h>
#include <math.h>
#include <stdint.h>

#define D_MODEL 2048
#define N_HEADS 16
#define HEAD_DIM 128
#define MLP_DIM 8192
#define BATCH 2
#define SEQ 2048
#define TOK (BATCH * SEQ)

typedef __half hf;

// ---------------- scratch (static device globals) ---------------------------
__device__ hf g_h[(size_t)TOK * D_MODEL];
__device__ hf g_q[(size_t)TOK * D_MODEL];
__device__ hf g_k[(size_t)TOK * D_MODEL];
__device__ hf g_v[(size_t)TOK * D_MODEL];
__device__ hf g_att[(size_t)TOK * D_MODEL];
__device__ hf g_up[(size_t)TOK * MLP_DIM];
__device__ float g_x1[(size_t)TOK * D_MODEL];
__device__ hf g_wq[(size_t)D_MODEL * D_MODEL];
__device__ hf g_wk[(size_t)D_MODEL * D_MODEL];
__device__ hf g_wv[(size_t)D_MODEL * D_MODEL];
__device__ hf g_wo[(size_t)D_MODEL * D_MODEL];
__device__ hf g_wu[(size_t)MLP_DIM * D_MODEL];
__device__ hf g_wd[(size_t)D_MODEL * MLP_DIM];

// ================= PTX helpers (baseline PTX, sm_80+) =======================
__device__ __forceinline__ uint32_t smem_to_u32(const void* p) {
    uint32_t a;
    asm("{ .reg .u64 t; cvta.to.shared.u64 t, %1; cvt.u32.u64 %0, t; }"
        : "=r"(a) : "l"(p));
    return a;
}
__device__ __forceinline__ void ldsm_x4(uint32_t addr, uint32_t* r) {
    asm volatile("ldmatrix.sync.aligned.m8n8.x4.shared.b16 {%0,%1,%2,%3}, [%4];"
                 : "=r"(r[0]), "=r"(r[1]), "=r"(r[2]), "=r"(r[3]) : "r"(addr));
}
__device__ __forceinline__ void mma_f16(float* d, const uint32_t* a,
                                        const uint32_t* b) {
    asm volatile(
        "mma.sync.aligned.m16n8k16.row.col.f32.f16.f16.f32 "
        "{%0,%1,%2,%3}, {%4,%5,%6,%7}, {%8,%9}, {%0,%1,%2,%3};"
        : "+f"(d[0]), "+f"(d[1]), "+f"(d[2]), "+f"(d[3])
        : "r"(a[0]), "r"(a[1]), "r"(a[2]), "r"(a[3]), "r"(b[0]), "r"(b[1]));
}
__device__ __forceinline__ uint32_t h2_bits(__half2 v) {
    return *reinterpret_cast<uint32_t*>(&v);
}
#define CP16(dst, src) \
    asm volatile("cp.async.cg.shared.global [%0], [%1], 16;" \
                 :: "r"(dst), "l"(src) : "memory")
#define CPCOMMIT() asm volatile("cp.async.commit_group;" ::: "memory")
#define CPWAIT(n)  asm volatile("cp.async.wait_group %0;" :: "n"(n) : "memory")

// ================= fused prep: weight rounding + rmsnorm1 ====================
#define DD4 (D_MODEL * D_MODEL / 4)      // 1048576 elems of float4
#define UD4 (MLP_DIM * D_MODEL / 4)      // 4194304
#define DD_BLK (DD4 / 256)               // 4096 blocks per d*d matrix
#define UD_BLK (UD4 / 256)               // 16384 blocks per mlp*d matrix
#define PREP_BLOCKS (4 * DD_BLK + 2 * UD_BLK + TOK)

__device__ __forceinline__ void round_store(const float* __restrict__ src,
                                            hf* __restrict__ dst, int i) {
    float4 v = reinterpret_cast<const float4*>(src)[i];
    __half2 a = __floats2half2_rn(v.x, v.y);
    __half2 b = __floats2half2_rn(v.z, v.w);
    reinterpret_cast<uint2*>(dst)[i] = make_uint2(h2_bits(a), h2_bits(b));
}

__device__ void rmsnorm_body(const float* __restrict__ xr_,
                             const float* __restrict__ w,
                             hf* __restrict__ out_row) {
    const float4* xr = reinterpret_cast<const float4*>(xr_);
    const float4* w4 = reinterpret_cast<const float4*>(w);
    float ss = 0.f;
    for (int i = threadIdx.x; i < D_MODEL / 4; i += blockDim.x) {
        float4 v = xr[i];
        ss += v.x * v.x + v.y * v.y + v.z * v.z + v.w * v.w;
    }
    for (int off = 16; off > 0; off >>= 1)
        ss += __shfl_xor_sync(0xFFFFFFFFu, ss, off);
    __shared__ float red[8];
    __shared__ float s_rms;
    int lane = threadIdx.x & 31, wid = threadIdx.x >> 5;
    if (lane == 0) red[wid] = ss;
    __syncthreads();
    if (threadIdx.x == 0) {
        float tt = 0.f;
        #pragma unroll
        for (int i = 0; i < 8; i++) tt += red[i];
        s_rms = rsqrtf(tt / (float)D_MODEL + 1e-6f);
    }
    __syncthreads();
    float r = s_rms;
    uint2* o2 = reinterpret_cast<uint2*>(out_row);
    for (int i = threadIdx.x; i < D_MODEL / 4; i += blockDim.x) {
        float4 v = xr[i];
        float4 ww = w4[i];
        __half2 a = __floats2half2_rn(v.x * r * ww.x, v.y * r * ww.y);
        __half2 b = __floats2half2_rn(v.z * r * ww.z, v.w * r * ww.w);
        o2[i] = make_uint2(h2_bits(a), h2_bits(b));
    }
}

__global__ void prep_all(const float* __restrict__ x,
                         const float* __restrict__ w_norm,
                         const float* __restrict__ wq, const float* __restrict__ wk,
                         const float* __restrict__ wv, const float* __restrict__ wo,
                         const float* __restrict__ wu, const float* __restrict__ wd,
                         hf* oq, hf* ok, hf* ov, hf* oo, hf* ou, hf* od,
                         hf* hout) {
    int bid = blockIdx.x;
    if (bid < 4 * DD_BLK) {
        int m = bid / DD_BLK;
        int i = (bid % DD_BLK) * 256 + threadIdx.x;
        switch (m) {
            case 0: round_store(wq, oq, i); break;
            case 1: round_store(wk, ok, i); break;
            case 2: round_store(wv, ov, i); break;
            default: round_store(wo, oo, i); break;
        }
        return;
    }
    bid -= 4 * DD_BLK;
    if (bid < 2 * UD_BLK) {
        int m = bid / UD_BLK;
        int i = (bid % UD_BLK) * 256 + threadIdx.x;
        if (m == 0) round_store(wu, ou, i);
        else        round_store(wd, od, i);
        return;
    }
    bid -= 2 * UD_BLK;
    rmsnorm_body(x + (size_t)bid * D_MODEL, w_norm,
                 hout + (size_t)bid * D_MODEL);
}

// standalone rmsnorm (2nd norm)
__global__ void rmsnorm_h(const float* __restrict__ x,
                          const float* __restrict__ w,
                          hf* __restrict__ out) {
    int row = blockIdx.x;
    rmsnorm_body(x + (size_t)row * D_MODEL, w, out + (size_t)row * D_MODEL);
}

// ================= FP16 GEMM (exact R11 config) ==============================
#define KC 64
#define ROWB 128
#define A_TILE 16384
#define B_TILE 32768
#define STAGE_B (A_TILE + B_TILE)
#define NSTAGE 4
#define GEMM_SMEM (NSTAGE * STAGE_B)   // 192 KB
#define GTHREADS 512

template <int EPI>
__device__ __forceinline__ void gemm_body(
    int Nc, int K, int m0, int c0,
    const hf* __restrict__ A, const hf* __restrict__ B,  // B pre-offset
    const float* __restrict__ RES, float* __restrict__ Cf,
    hf* __restrict__ Ch) {
    extern __shared__ char smem[];
    const uint32_t su = smem_to_u32(smem);

    const int t = threadIdx.x;
    const int lane = t & 31;
    const int wid = t >> 5;
    const int wm = wid & 3;
    const int wn = wid >> 2;

    const int arow = t >> 2;
    const int aseg = t & 3;
    const hf* Asrc = A + (size_t)(m0 + arow) * K + aseg * 16;
    const uint32_t asw = ((uint32_t)(arow & 7)) << 4;
    const uint32_t adst = (uint32_t)arow * ROWB;

    const int brow = t >> 1;
    const int bhalf = t & 1;
    const hf* Bsrc = B + (size_t)brow * K + bhalf * 32;
    const uint32_t bsw = ((uint32_t)(brow & 7)) << 4;
    const uint32_t bdst = (uint32_t)A_TILE + (uint32_t)brow * ROWB;

    auto CP_chunk = [&](int s, int k0) {
        const uint32_t st = su + (uint32_t)s * STAGE_B;
        #pragma unroll
        for (int c = 0; c < 2; c++)
            CP16(st + adst + (((uint32_t)(aseg * 32 + c * 16)) ^ asw),
                 Asrc + k0 + c * 8);
        #pragma unroll
        for (int c = 0; c < 4; c++)
            CP16(st + bdst + (((uint32_t)(bhalf * 64 + c * 16)) ^ bsw),
                 Bsrc + k0 + c * 8);
    };

    float acc[2][8][4];
    #pragma unroll
    for (int mt = 0; mt < 2; mt++)
        #pragma unroll
        for (int nt = 0; nt < 8; nt++)
            #pragma unroll
            for (int j = 0; j < 4; j++) acc[mt][nt][j] = 0.f;

    const int nch = K / KC;
    #pragma unroll
    for (int s = 0; s < NSTAGE - 1; s++) {
        CP_chunk(s, s * KC);
        CPCOMMIT();
    }

    const int lrow16 = lane & 15;
    const int cg = (lane >> 4) & 1;

    for (int i = 0; i < nch; i++) {
        CPWAIT(NSTAGE - 2);
        __syncthreads();

        const uint32_t st = su + (uint32_t)(i % NSTAGE) * STAGE_B;

        #pragma unroll
        for (int ks = 0; ks < 4; ks++) {
            const uint32_t cbh = (uint32_t)(ks * 32 + cg * 16);
            uint32_t Af[2][4];
            #pragma unroll
            for (int mt = 0; mt < 2; mt++) {
                const int row = wm * 32 + mt * 16 + lrow16;
                const uint32_t swz = (uint32_t)(row & 7) << 4;
                ldsm_x4(st + (uint32_t)row * ROWB + (cbh ^ swz), Af[mt]);
            }
            #pragma unroll
            for (int q = 0; q < 4; q++) {
                const int row = wn * 64 + q * 16 + lrow16;
                const uint32_t swz = (uint32_t)(row & 7) << 4;
                uint32_t r[4];
                ldsm_x4(st + A_TILE + (uint32_t)row * ROWB + (cbh ^ swz), r);
                uint32_t b0[2] = {r[0], r[2]};
                uint32_t b1[2] = {r[1], r[3]};
                #pragma unroll
                for (int mt = 0; mt < 2; mt++) {
                    mma_f16(acc[mt][2 * q + 0], Af[mt], b0);
                    mma_f16(acc[mt][2 * q + 1], Af[mt], b1);
                }
            }
        }

        if (i + NSTAGE - 1 < nch)
            CP_chunk((i + NSTAGE - 1) % NSTAGE, (i + NSTAGE - 1) * KC);
        CPCOMMIT();
    }

    const int er0 = m0 + wm * 32 + (lane >> 2);
    const int ec0 = c0 + wn * 64 + (lane & 3) * 2;
    #pragma unroll
    for (int mt = 0; mt < 2; mt++) {
        #pragma unroll
        for (int g = 0; g < 2; g++) {
            const int row = er0 + mt * 16 + g * 8;
            #pragma unroll
            for (int nt = 0; nt < 8; nt++) {
                const int col = ec0 + nt * 8;
                float v0 = acc[mt][nt][g * 2 + 0];
                float v1 = acc[mt][nt][g * 2 + 1];
                size_t roff = (size_t)row * Nc + col;
                if (EPI == 2) {
                    float2 r = *reinterpret_cast<const float2*>(RES + roff);
                    *reinterpret_cast<float2*>(Cf + roff) =
                        make_float2(v0 + r.x, v1 + r.y);
                } else {
                    if (EPI == 1) {
                        v0 = 0.5f * v0 * (1.0f + erff(v0 * 0.70710678118654752f));
                        v1 = 0.5f * v1 * (1.0f + erff(v1 * 0.70710678118654752f));
                    }
                    *reinterpret_cast<uint32_t*>(Ch + roff) =
                        h2_bits(__floats2half2_rn(v0, v1));
                }
            }
        }
    }
}

template <int EPI>
__global__ void __launch_bounds__(GTHREADS, 1)
mma_gemm(int N, int K,
         const hf* __restrict__ A, const hf* __restrict__ B,
         const float* __restrict__ RES, float* __restrict__ Cf,
         hf* __restrict__ Ch) {
    const int n0 = blockIdx.x * 256;
    gemm_body<EPI>(N, K, blockIdx.y * 128, n0, A, B + (size_t)n0 * K,
                   RES, Cf, Ch);
}

__global__ void __launch_bounds__(GTHREADS, 1)
qkv_gemm(const hf* __restrict__ h,
         const hf* __restrict__ wq, const hf* __restrict__ wk,
         const hf* __restrict__ wv,
         hf* __restrict__ q, hf* __restrict__ k, hf* __restrict__ v) {
    const int n0g = blockIdx.x * 256;
    const int sel = n0g >> 11;
    const int n0 = n0g & 2047;
    const hf* B;
    hf* C;
    if (sel == 0)      { B = wq; C = q; }
    else if (sel == 1) { B = wk; C = k; }
    else               { B = wv; C = v; }
    gemm_body<0>(D_MODEL, D_MODEL, blockIdx.y * 128, n0,
                 h, B + (size_t)n0 * D_MODEL, nullptr, nullptr, C);
}

// ================= FP16 flash attention, BKV=128 (R14 core) ==================
#define ATT_BUF0 65536
#define ATT_MASK 131072
#define ATT_SMEM_BYTES (131072 + 1024)

__device__ __forceinline__ void att_stage(
    char* smem, uint32_t sb, uint32_t bufoff,
    const hf* __restrict__ Kg, const hf* __restrict__ Vg,
    const int* __restrict__ bm, int kv0, int slot, int t) {
    {
        const int row = t >> 1;
        const int dq = (t & 1) * 64;
        const size_t goff = (size_t)(kv0 + row) * D_MODEL + dq;
        const uint32_t rbase = sb + bufoff + (uint32_t)row * 256;
        const uint32_t swr = ((uint32_t)(row & 7)) << 4;
        #pragma unroll
        for (int i = 0; i < 8; i++)
            CP16(rbase + (((uint32_t)(dq * 2 + i * 16)) ^ swr),
                 Kg + goff + i * 8);
    }
    {
        const int kvp = t & 63;
        const int dblk = t >> 6;
        const size_t r0 = (size_t)(kv0 + 2 * kvp) * D_MODEL + dblk * 32;
        const size_t r1 = r0 + D_MODEL;
        uint32_t h0[16], h1[16];
        #pragma unroll
        for (int c = 0; c < 4; c++) {
            uint4 a = *reinterpret_cast<const uint4*>(Vg + r0 + c * 8);
            uint4 b = *reinterpret_cast<const uint4*>(Vg + r1 + c * 8);
            h0[c * 4 + 0] = a.x; h0[c * 4 + 1] = a.y;
            h0[c * 4 + 2] = a.z; h0[c * 4 + 3] = a.w;
            h1[c * 4 + 0] = b.x; h1[c * 4 + 1] = b.y;
            h1[c * 4 + 2] = b.z; h1[c * 4 + 3] = b.w;
        }
        const uint32_t koff = (uint32_t)(kvp * 4);
        #pragma unroll
        for (int dd = 0; dd < 16; dd++) {
            const int d0 = dblk * 32 + dd * 2;
            const uint32_t vb0 = sb + bufoff + 32768 + (uint32_t)d0 * 256 +
                                 (koff ^ ((uint32_t)(d0 & 7) << 4));
            const uint32_t vb1 = sb + bufoff + 32768 + (uint32_t)(d0 + 1) * 256 +
                                 (koff ^ ((uint32_t)((d0 + 1) & 7) << 4));
            asm volatile("st.shared.b32 [%0], %1;" :: "r"(vb0),
                         "r"(__byte_perm(h0[dd], h1[dd], 0x5410)) : "memory");
            asm volatile("st.shared.b32 [%0], %1;" :: "r"(vb1),
                         "r"(__byte_perm(h0[dd], h1[dd], 0x7632)) : "memory");
        }
    }
    if (t < 128)
        reinterpret_cast<int*>(smem + ATT_MASK + slot * 512)[t] = bm[kv0 + t];
}

__global__ void __launch_bounds__(256, 1)
flash_attn_h(const hf* __restrict__ Q, const hf* __restrict__ K,
             const hf* __restrict__ V, const int* __restrict__ mask,
             hf* __restrict__ O) {
    extern __shared__ char smem[];
    const uint32_t sb = smem_to_u32(smem);
    const int t = threadIdx.x, lane = t & 31, w = t >> 5;
    const int qi = gridDim.x - 1 - blockIdx.x;
    const int h = blockIdx.y, b = blockIdx.z;
    const int q0 = qi * 128;
    const size_t base = (size_t)b * SEQ * D_MODEL + (size_t)h * HEAD_DIM;
    const int* bm = mask + b * SEQ;
    const float scale = 0.08838834764831845f;

    {
        const int row = t >> 1, half = t & 1;
        const uint4* gq = reinterpret_cast<const uint4*>(
            Q + base + (size_t)(q0 + row) * D_MODEL + half * 64);
        char* qr = smem + (uint32_t)row * 256;
        const uint32_t swr = ((uint32_t)(row & 7)) << 4;
        #pragma unroll
        for (int i = 0; i < 8; i++)
            *reinterpret_cast<uint4*>(
                qr + (((uint32_t)(half * 128 + i * 16)) ^ swr)) = gq[i];
    }
    att_stage(smem, sb, ATT_BUF0, K + base, V + base, bm, 0, 0, t);
    CPCOMMIT();
    CPWAIT(0);
    __syncthreads();

    uint32_t Aq[8][4];
    {
        const int r = w * 16 + (lane & 15);
        const uint32_t swz = ((uint32_t)(r & 7)) << 4;
        const uint32_t cgo = ((uint32_t)(lane >> 4)) << 4;
        const uint32_t qb = sb + (uint32_t)r * 256;
        #pragma unroll
        for (int ds = 0; ds < 8; ds++)
            ldsm_x4(qb + ((((uint32_t)(ds * 32)) + cgo) ^ swz), Aq[ds]);
    }
    __syncthreads();

    float m1 = -1e30f, l1 = 0.f, m2 = -1e30f, l2 = 0.f;
    float acc[16][4];
    #pragma unroll
    for (int nt = 0; nt < 16; nt++)
        #pragma unroll
        for (int c = 0; c < 4; c++) acc[nt][c] = 0.f;

    const int r1g = q0 + w * 16 + (lane >> 2);
    const int r2g = r1g + 8;
    const int nch = qi + 1;
    const uint32_t cgo = ((uint32_t)(lane >> 4)) << 4;

    for (int j = 0; j < nch; j++) {
        const int s = j & 1;
        const uint32_t bufo = s ? 0u : (uint32_t)ATT_BUF0;
        const int kv0 = j * 128;

        if (j + 1 < nch) {
            att_stage(smem, sb, s ? (uint32_t)ATT_BUF0 : 0u,
                      K + base, V + base, bm, kv0 + 128, (j + 1) & 1, t);
            CPCOMMIT();
        }

        float sacc[16][4];
        #pragma unroll
        for (int nt = 0; nt < 16; nt++)
            #pragma unroll
            for (int c = 0; c < 4; c++) sacc[nt][c] = 0.f;

        #pragma unroll
        for (int g4 = 0; g4 < 8; g4++) {
            const int kr = g4 * 16 + (lane & 15);
            const uint32_t swz = ((uint32_t)(kr & 7)) << 4;
            const uint32_t kb = sb + bufo + (uint32_t)kr * 256;
            #pragma unroll
            for (int ds = 0; ds < 8; ds++) {
                uint32_t r[4];
                ldsm_x4(kb + ((((uint32_t)(ds * 32)) + cgo) ^ swz), r);
                uint32_t b0[2] = {r[0], r[2]};
                uint32_t b1[2] = {r[1], r[3]};
                mma_f16(sacc[2 * g4 + 0], Aq[ds], b0);
                mma_f16(sacc[2 * g4 + 1], Aq[ds], b1);
            }
        }

        const int* mrow = reinterpret_cast<const int*>(smem + ATT_MASK + s * 512);
        #pragma unroll
        for (int nt = 0; nt < 16; nt++) {
            const int c0 = nt * 8 + (lane & 3) * 2;
            const int k0g = kv0 + c0, k1g = k0g + 1;
            const bool mv0 = mrow[c0] != 0, mv1 = mrow[c0 + 1] != 0;
            float v0 = sacc[nt][0] * scale, v1 = sacc[nt][1] * scale;
            float v2 = sacc[nt][2] * scale, v3 = sacc[nt][3] * scale;
            sacc[nt][0] = (k0g > r1g || !mv0) ? -1e9f : v0;
            sacc[nt][1] = (k1g > r1g || !mv1) ? -1e9f : v1;
            sacc[nt][2] = (k0g > r2g || !mv0) ? -1e9f : v2;
            sacc[nt][3] = (k1g > r2g || !mv1) ? -1e9f : v3;
        }

        float mx1 = -1e30f, mx2 = -1e30f;
        #pragma unroll
        for (int nt = 0; nt < 16; nt++) {
            mx1 = fmaxf(mx1, fmaxf(sacc[nt][0], sacc[nt][1]));
            mx2 = fmaxf(mx2, fmaxf(sacc[nt][2], sacc[nt][3]));
        }
        mx1 = fmaxf(mx1, __shfl_xor_sync(0xFFFFFFFFu, mx1, 1));
        mx1 = fmaxf(mx1, __shfl_xor_sync(0xFFFFFFFFu, mx1, 2));
        mx2 = fmaxf(mx2, __shfl_xor_sync(0xFFFFFFFFu, mx2, 1));
        mx2 = fmaxf(mx2, __shfl_xor_sync(0xFFFFFFFFu, mx2, 2));
        const float m1n = fmaxf(m1, mx1), m2n = fmaxf(m2, mx2);
        float s1 = 0.f, s2 = 0.f;
        #pragma unroll
        for (int nt = 0; nt < 16; nt++) {
            sacc[nt][0] = __expf(sacc[nt][0] - m1n);
            sacc[nt][1] = __expf(sacc[nt][1] - m1n);
            sacc[nt][2] = __expf(sacc[nt][2] - m2n);
            sacc[nt][3] = __expf(sacc[nt][3] - m2n);
            s1 += sacc[nt][0] + sacc[nt][1];
            s2 += sacc[nt][2] + sacc[nt][3];
        }
        s1 += __shfl_xor_sync(0xFFFFFFFFu, s1, 1);
        s1 += __shfl_xor_sync(0xFFFFFFFFu, s1, 2);
        s2 += __shfl_xor_sync(0xFFFFFFFFu, s2, 1);
        s2 += __shfl_xor_sync(0xFFFFFFFFu, s2, 2);
        if (j) {
            const float a1 = __expf(m1 - m1n), a2 = __expf(m2 - m2n);
            l1 = l1 * a1 + s1;
            l2 = l2 * a2 + s2;
            #pragma unroll
            for (int nt = 0; nt < 16; nt++) {
                acc[nt][0] *= a1; acc[nt][1] *= a1;
                acc[nt][2] *= a2; acc[nt][3] *= a2;
            }
        } else {
            l1 = s1;
            l2 = s2;
        }
        m1 = m1n;
        m2 = m2n;

        #pragma unroll
        for (int ks = 0; ks < 8; ks++) {
            const float* p0 = sacc[2 * ks];
            const float* p1 = sacc[2 * ks + 1];
            uint32_t pa[4];
            pa[0] = h2_bits(__floats2half2_rn(p0[0], p0[1]));
            pa[1] = h2_bits(__floats2half2_rn(p0[2], p0[3]));
            pa[2] = h2_bits(__floats2half2_rn(p1[0], p1[1]));
            pa[3] = h2_bits(__floats2half2_rn(p1[2], p1[3]));

            #pragma unroll
            for (int gd = 0; gd < 8; gd++) {
                const int dr = gd * 16 + (lane & 15);
                const uint32_t swz = ((uint32_t)(dr & 7)) << 4;
                const uint32_t vb = sb + bufo + 32768 + (uint32_t)dr * 256;
                uint32_t r[4];
                ldsm_x4(vb + ((((uint32_t)(ks * 32)) + cgo) ^ swz), r);
                uint32_t b0[2] = {r[0], r[2]};
                uint32_t b1[2] = {r[1], r[3]};
                mma_f16(acc[2 * gd + 0], pa, b0);
                mma_f16(acc[2 * gd + 1], pa, b1);
            }
        }

        CPWAIT(0);
        __syncthreads();
    }

    const float i1 = (l1 > 0.f) ? 1.f / l1 : 0.f;
    const float i2 = (l2 > 0.f) ? 1.f / l2 : 0.f;
    #pragma unroll
    for (int nt = 0; nt < 16; nt++) {
        const int col = nt * 8 + (lane & 3) * 2;
        *reinterpret_cast<uint32_t*>(O + base + (size_t)r1g * D_MODEL + col) =
            h2_bits(__floats2half2_rn(acc[nt][0] * i1, acc[nt][1] * i1));
        *reinterpret_cast<uint32_t*>(O + base + (size_t)r2g * D_MODEL + col) =
            h2_bits(__floats2half2_rn(acc[nt][2] * i2, acc[nt][3] * i2));
    }
}

// ---------------- launch -----------------------------------------------------
extern "C" void kernel_launch(void* const* d_in, const int* in_sizes, int n_in,
                              void* d_out, int out_size) {
    const float* x           = (const float*)d_in[0];
    const int*   attn_mask   = (const int*)  d_in[1];
    const float* w_norm_attn = (const float*)d_in[2];
    const float* wq          = (const float*)d_in[3];
    const float* wk          = (const float*)d_in[4];
    const float* wv          = (const float*)d_in[5];
    const float* wo          = (const float*)d_in[6];
    const float* w_norm_mlp  = (const float*)d_in[7];
    const float* w_up        = (const float*)d_in[8];
    const float* w_down      = (const float*)d_in[9];
    float* out = (float*)d_out;

    hf *h, *q, *k, *v, *att, *up;
    hf *rwq, *rwk, *rwv, *rwo, *rwu, *rwd;
    float* x1;
    cudaGetSymbolAddress((void**)&h, g_h);
    cudaGetSymbolAddress((void**)&q, g_q);
    cudaGetSymbolAddress((void**)&k, g_k);
    cudaGetSymbolAddress((void**)&v, g_v);
    cudaGetSymbolAddress((void**)&att, g_att);
    cudaGetSymbolAddress((void**)&up, g_up);
    cudaGetSymbolAddress((void**)&x1, g_x1);
    cudaGetSymbolAddress((void**)&rwq, g_wq);
    cudaGetSymbolAddress((void**)&rwk, g_wk);
    cudaGetSymbolAddress((void**)&rwv, g_wv);
    cudaGetSymbolAddress((void**)&rwo, g_wo);
    cudaGetSymbolAddress((void**)&rwu, g_wu);
    cudaGetSymbolAddress((void**)&rwd, g_wd);

    cudaFuncSetAttribute(flash_attn_h,
                         cudaFuncAttributeMaxDynamicSharedMemorySize, ATT_SMEM_BYTES);
    cudaFuncSetAttribute(qkv_gemm,
                         cudaFuncAttributeMaxDynamicSharedMemorySize, GEMM_SMEM);
    cudaFuncSetAttribute(mma_gemm<1>,
                         cudaFuncAttributeMaxDynamicSharedMemorySize, GEMM_SMEM);
    cudaFuncSetAttribute(mma_gemm<2>,
                         cudaFuncAttributeMaxDynamicSharedMemorySize, GEMM_SMEM);

    // 0+1) fused: round all weights to fp16 + rmsnorm(x) -> h
    prep_all<<<PREP_BLOCKS, 256>>>(x, w_norm_attn, wq, wk, wv, wo, w_up, w_down,
                                   rwq, rwk, rwv, rwo, rwu, rwd, h);

    // 2) fused q,k,v projection
    dim3 gQKV(3 * D_MODEL / 256, TOK / 128);
    qkv_gemm<<<gQKV, GTHREADS, GEMM_SMEM>>>(h, rwq, rwk, rwv, q, k, v);

    // 3) attention (BKV=128)
    dim3 gA(SEQ / 128, N_HEADS, BATCH);
    flash_attn_h<<<gA, 256, ATT_SMEM_BYTES>>>(q, k, v, attn_mask, att);

    // 4) output projection + residual -> x1 (fp32)
    dim3 gD(D_MODEL / 256, TOK / 128);
    mma_gemm<2><<<gD, GTHREADS, GEMM_SMEM>>>(D_MODEL, D_MODEL,
                                             att, rwo, x, x1, nullptr);

    // 5) rmsnorm(x1) -> h
    rmsnorm_h<<<TOK, 256>>>(x1, w_norm_mlp, h);

    // 6) up projection + gelu (fp16 store)
    dim3 gU(MLP_DIM / 256, TOK / 128);
    mma_gemm<1><<<gU, GTHREADS, GEMM_SMEM>>>(MLP_DIM, D_MODEL,
                                             h, rwu, nullptr, nullptr, up);

    // 7) down projection + residual -> out (fp32)
    mma_gemm<2><<<gD, GTHREADS, GEMM_SMEM>>>(D_MODEL, MLP_DIM,
                                             up, rwd, x1, out, nullptr);
}

// round 16
// speedup vs baseline: 1.0220x; 1.0220x over previous
#include <cuda_runtime.h>
#include <cuda_fp16.h>
#include <math.h>
#include <stdint.h>

#define D_MODEL 2048
#define N_HEADS 16
#define HEAD_DIM 128
#define MLP_DIM 8192
#define BATCH 2
#define SEQ 2048
#define TOK (BATCH * SEQ)

typedef __half hf;

// ---------------- scratch (static device globals) ---------------------------
__device__ hf g_h[(size_t)TOK * D_MODEL];
__device__ hf g_q[(size_t)TOK * D_MODEL];
__device__ hf g_k[(size_t)TOK * D_MODEL];
__device__ hf g_v[(size_t)TOK * D_MODEL];
__device__ hf g_att[(size_t)TOK * D_MODEL];
__device__ hf g_up[(size_t)TOK * MLP_DIM];
__device__ float g_x1[(size_t)TOK * D_MODEL];
__device__ hf g_wq[(size_t)D_MODEL * D_MODEL];
__device__ hf g_wk[(size_t)D_MODEL * D_MODEL];
__device__ hf g_wv[(size_t)D_MODEL * D_MODEL];
__device__ hf g_wo[(size_t)D_MODEL * D_MODEL];
__device__ hf g_wu[(size_t)MLP_DIM * D_MODEL];
__device__ hf g_wd[(size_t)D_MODEL * MLP_DIM];

// ================= PTX helpers (baseline PTX, sm_80+) =======================
__device__ __forceinline__ uint32_t smem_to_u32(const void* p) {
    uint32_t a;
    asm("{ .reg .u64 t; cvta.to.shared.u64 t, %1; cvt.u32.u64 %0, t; }"
        : "=r"(a) : "l"(p));
    return a;
}
__device__ __forceinline__ void ldsm_x4(uint32_t addr, uint32_t* r) {
    asm volatile("ldmatrix.sync.aligned.m8n8.x4.shared.b16 {%0,%1,%2,%3}, [%4];"
                 : "=r"(r[0]), "=r"(r[1]), "=r"(r[2]), "=r"(r[3]) : "r"(addr));
}
__device__ __forceinline__ void mma_f16(float* d, const uint32_t* a,
                                        const uint32_t* b) {
    asm volatile(
        "mma.sync.aligned.m16n8k16.row.col.f32.f16.f16.f32 "
        "{%0,%1,%2,%3}, {%4,%5,%6,%7}, {%8,%9}, {%0,%1,%2,%3};"
        : "+f"(d[0]), "+f"(d[1]), "+f"(d[2]), "+f"(d[3])
        : "r"(a[0]), "r"(a[1]), "r"(a[2]), "r"(a[3]), "r"(b[0]), "r"(b[1]));
}
__device__ __forceinline__ uint32_t h2_bits(__half2 v) {
    return *reinterpret_cast<uint32_t*>(&v);
}
#define CP16(dst, src) \
    asm volatile("cp.async.cg.shared.global [%0], [%1], 16;" \
                 :: "r"(dst), "l"(src) : "memory")
#define CPCOMMIT() asm volatile("cp.async.commit_group;" ::: "memory")
#define CPWAIT(n)  asm volatile("cp.async.wait_group %0;" :: "n"(n) : "memory")

// fast exact-erf gelu (Abramowitz-Stegun 7.1.26, |eps|<=1.5e-7)
__device__ __forceinline__ float gelu_f(float x) {
    const float xs = x * 0.70710678118654752f;
    const float ax = fabsf(xs);
    const float t = __frcp_rn(fmaf(0.3275911f, ax, 1.0f));
    float poly = fmaf(1.061405429f, t, -1.453152027f);
    poly = fmaf(poly, t, 1.421413741f);
    poly = fmaf(poly, t, -0.284496736f);
    poly = fmaf(poly, t, 0.254829592f);
    const float e = __expf(-ax * ax);
    float erfv = 1.0f - poly * t * e;
    erfv = (xs < 0.f) ? -erfv : erfv;
    return 0.5f * x * (1.0f + erfv);
}

// ================= weight rounding fp32 -> fp16 (once) =======================
__device__ __forceinline__ void round_store(const float* __restrict__ src,
                                            hf* __restrict__ dst, int i) {
    float4 v = reinterpret_cast<const float4*>(src)[i];
    __half2 a = __floats2half2_rn(v.x, v.y);
    __half2 b = __floats2half2_rn(v.z, v.w);
    reinterpret_cast<uint2*>(dst)[i] = make_uint2(h2_bits(a), h2_bits(b));
}
__global__ void round_dd(const float* __restrict__ wq, const float* __restrict__ wk,
                         const float* __restrict__ wv, const float* __restrict__ wo,
                         hf* oq, hf* ok, hf* ov, hf* oo) {
    int i = blockIdx.x * blockDim.x + threadIdx.x;
    if (i >= D_MODEL * D_MODEL / 4) return;
    switch (blockIdx.y) {
        case 0: round_store(wq, oq, i); break;
        case 1: round_store(wk, ok, i); break;
        case 2: round_store(wv, ov, i); break;
        default: round_store(wo, oo, i); break;
    }
}
__global__ void round_ud(const float* __restrict__ wu, const float* __restrict__ wd,
                         hf* ou, hf* od) {
    int i = blockIdx.x * blockDim.x + threadIdx.x;
    if (i >= MLP_DIM * D_MODEL / 4) return;
    if (blockIdx.y == 0) round_store(wu, ou, i);
    else                 round_store(wd, od, i);
}

// ================= RMSNorm -> fp16, one warp per row =========================
__global__ void __launch_bounds__(256)
rmsnorm_h(const float* __restrict__ x, const float* __restrict__ w,
          hf* __restrict__ out) {
    const int lane = threadIdx.x & 31;
    const int row = blockIdx.x * 8 + (threadIdx.x >> 5);
    const float4* xr = reinterpret_cast<const float4*>(x + (size_t)row * D_MODEL);
    const float4* w4 = reinterpret_cast<const float4*>(w);

    float4 v[16];
    float ss = 0.f;
    #pragma unroll
    for (int i = 0; i < 16; i++) {
        v[i] = xr[lane + i * 32];
        ss += v[i].x * v[i].x + v[i].y * v[i].y +
              v[i].z * v[i].z + v[i].w * v[i].w;
    }
    #pragma unroll
    for (int off = 16; off > 0; off >>= 1)
        ss += __shfl_xor_sync(0xFFFFFFFFu, ss, off);
    const float r = rsqrtf(ss / (float)D_MODEL + 1e-6f);

    uint2* o2 = reinterpret_cast<uint2*>(out + (size_t)row * D_MODEL);
    #pragma unroll
    for (int i = 0; i < 16; i++) {
        float4 ww = w4[lane + i * 32];
        __half2 a = __floats2half2_rn(v[i].x * r * ww.x, v[i].y * r * ww.y);
        __half2 b = __floats2half2_rn(v[i].z * r * ww.z, v[i].w * r * ww.w);
        o2[lane + i * 32] = make_uint2(h2_bits(a), h2_bits(b));
    }
}

// ================= FP16 GEMM (exact R11 config) ==============================
#define KC 64
#define ROWB 128
#define A_TILE 16384
#define B_TILE 32768
#define STAGE_B (A_TILE + B_TILE)
#define NSTAGE 4
#define GEMM_SMEM (NSTAGE * STAGE_B)   // 192 KB
#define GTHREADS 512

template <int EPI>
__device__ __forceinline__ void gemm_body(
    int Nc, int K, int m0, int c0,
    const hf* __restrict__ A, const hf* __restrict__ B,  // B pre-offset
    const float* __restrict__ RES, float* __restrict__ Cf,
    hf* __restrict__ Ch) {
    extern __shared__ char smem[];
    const uint32_t su = smem_to_u32(smem);

    const int t = threadIdx.x;
    const int lane = t & 31;
    const int wid = t >> 5;
    const int wm = wid & 3;
    const int wn = wid >> 2;

    const int arow = t >> 2;
    const int aseg = t & 3;
    const hf* Asrc = A + (size_t)(m0 + arow) * K + aseg * 16;
    const uint32_t asw = ((uint32_t)(arow & 7)) << 4;
    const uint32_t adst = (uint32_t)arow * ROWB;

    const int brow = t >> 1;
    const int bhalf = t & 1;
    const hf* Bsrc = B + (size_t)brow * K + bhalf * 32;
    const uint32_t bsw = ((uint32_t)(brow & 7)) << 4;
    const uint32_t bdst = (uint32_t)A_TILE + (uint32_t)brow * ROWB;

    auto CP_chunk = [&](int s, int k0) {
        const uint32_t st = su + (uint32_t)s * STAGE_B;
        #pragma unroll
        for (int c = 0; c < 2; c++)
            CP16(st + adst + (((uint32_t)(aseg * 32 + c * 16)) ^ asw),
                 Asrc + k0 + c * 8);
        #pragma unroll
        for (int c = 0; c < 4; c++)
            CP16(st + bdst + (((uint32_t)(bhalf * 64 + c * 16)) ^ bsw),
                 Bsrc + k0 + c * 8);
    };

    float acc[2][8][4];
    #pragma unroll
    for (int mt = 0; mt < 2; mt++)
        #pragma unroll
        for (int nt = 0; nt < 8; nt++)
            #pragma unroll
            for (int j = 0; j < 4; j++) acc[mt][nt][j] = 0.f;

    const int nch = K / KC;
    #pragma unroll
    for (int s = 0; s < NSTAGE - 1; s++) {
        CP_chunk(s, s * KC);
        CPCOMMIT();
    }

    const int lrow16 = lane & 15;
    const int cg = (lane >> 4) & 1;

    for (int i = 0; i < nch; i++) {
        CPWAIT(NSTAGE - 2);
        __syncthreads();

        const uint32_t st = su + (uint32_t)(i % NSTAGE) * STAGE_B;

        #pragma unroll
        for (int ks = 0; ks < 4; ks++) {
            const uint32_t cbh = (uint32_t)(ks * 32 + cg * 16);
            uint32_t Af[2][4];
            #pragma unroll
            for (int mt = 0; mt < 2; mt++) {
                const int row = wm * 32 + mt * 16 + lrow16;
                const uint32_t swz = (uint32_t)(row & 7) << 4;
                ldsm_x4(st + (uint32_t)row * ROWB + (cbh ^ swz), Af[mt]);
            }
            #pragma unroll
            for (int q = 0; q < 4; q++) {
                const int row = wn * 64 + q * 16 + lrow16;
                const uint32_t swz = (uint32_t)(row & 7) << 4;
                uint32_t r[4];
                ldsm_x4(st + A_TILE + (uint32_t)row * ROWB + (cbh ^ swz), r);
                uint32_t b0[2] = {r[0], r[2]};
                uint32_t b1[2] = {r[1], r[3]};
                #pragma unroll
                for (int mt = 0; mt < 2; mt++) {
                    mma_f16(acc[mt][2 * q + 0], Af[mt], b0);
                    mma_f16(acc[mt][2 * q + 1], Af[mt], b1);
                }
            }
        }

        if (i + NSTAGE - 1 < nch)
            CP_chunk((i + NSTAGE - 1) % NSTAGE, (i + NSTAGE - 1) * KC);
        CPCOMMIT();
    }

    const int er0 = m0 + wm * 32 + (lane >> 2);
    const int ec0 = c0 + wn * 64 + (lane & 3) * 2;
    #pragma unroll
    for (int mt = 0; mt < 2; mt++) {
        #pragma unroll
        for (int g = 0; g < 2; g++) {
            const int row = er0 + mt * 16 + g * 8;
            #pragma unroll
            for (int nt = 0; nt < 8; nt++) {
                const int col = ec0 + nt * 8;
                float v0 = acc[mt][nt][g * 2 + 0];
                float v1 = acc[mt][nt][g * 2 + 1];
                size_t roff = (size_t)row * Nc + col;
                if (EPI == 2) {
                    float2 r = *reinterpret_cast<const float2*>(RES + roff);
                    *reinterpret_cast<float2*>(Cf + roff) =
                        make_float2(v0 + r.x, v1 + r.y);
                } else {
                    if (EPI == 1) {
                        v0 = gelu_f(v0);
                        v1 = gelu_f(v1);
                    }
                    *reinterpret_cast<uint32_t*>(Ch + roff) =
                        h2_bits(__floats2half2_rn(v0, v1));
                }
            }
        }
    }
}

template <int EPI>
__global__ void __launch_bounds__(GTHREADS, 1)
mma_gemm(int N, int K,
         const hf* __restrict__ A, const hf* __restrict__ B,
         const float* __restrict__ RES, float* __restrict__ Cf,
         hf* __restrict__ Ch) {
    const int n0 = blockIdx.x * 256;
    gemm_body<EPI>(N, K, blockIdx.y * 128, n0, A, B + (size_t)n0 * K,
                   RES, Cf, Ch);
}

__global__ void __launch_bounds__(GTHREADS, 1)
qkv_gemm(const hf* __restrict__ h,
         const hf* __restrict__ wq, const hf* __restrict__ wk,
         const hf* __restrict__ wv,
         hf* __restrict__ q, hf* __restrict__ k, hf* __restrict__ v) {
    const int n0g = blockIdx.x * 256;
    const int sel = n0g >> 11;
    const int n0 = n0g & 2047;
    const hf* B;
    hf* C;
    if (sel == 0)      { B = wq; C = q; }
    else if (sel == 1) { B = wk; C = k; }
    else               { B = wv; C = v; }
    gemm_body<0>(D_MODEL, D_MODEL, blockIdx.y * 128, n0,
                 h, B + (size_t)n0 * D_MODEL, nullptr, nullptr, C);
}

// ================= FP16 flash attention, BKV=128 =============================
#define ATT_BUF0 65536
#define ATT_MASK 131072
#define ATT_SMEM_BYTES (131072 + 1024)

__device__ __forceinline__ void att_stage(
    char* smem, uint32_t sb, uint32_t bufoff,
    const hf* __restrict__ Kg, const hf* __restrict__ Vg,
    const int* __restrict__ bm, int kv0, int slot, int t) {
    {
        const int row = t >> 1;
        const int dq = (t & 1) * 64;
        const size_t goff = (size_t)(kv0 + row) * D_MODEL + dq;
        const uint32_t rbase = sb + bufoff + (uint32_t)row * 256;
        const uint32_t swr = ((uint32_t)(row & 7)) << 4;
        #pragma unroll
        for (int i = 0; i < 8; i++)
            CP16(rbase + (((uint32_t)(dq * 2 + i * 16)) ^ swr),
                 Kg + goff + i * 8);
    }
    {
        const int kvp = t & 63;
        const int dblk = t >> 6;
        const size_t r0 = (size_t)(kv0 + 2 * kvp) * D_MODEL + dblk * 32;
        const size_t r1 = r0 + D_MODEL;
        uint32_t h0[16], h1[16];
        #pragma unroll
        for (int c = 0; c < 4; c++) {
            uint4 a = *reinterpret_cast<const uint4*>(Vg + r0 + c * 8);
            uint4 b = *reinterpret_cast<const uint4*>(Vg + r1 + c * 8);
            h0[c * 4 + 0] = a.x; h0[c * 4 + 1] = a.y;
            h0[c * 4 + 2] = a.z; h0[c * 4 + 3] = a.w;
            h1[c * 4 + 0] = b.x; h1[c * 4 + 1] = b.y;
            h1[c * 4 + 2] = b.z; h1[c * 4 + 3] = b.w;
        }
        const uint32_t koff = (uint32_t)(kvp * 4);
        #pragma unroll
        for (int dd = 0; dd < 16; dd++) {
            const int d0 = dblk * 32 + dd * 2;
            const uint32_t vb0 = sb + bufoff + 32768 + (uint32_t)d0 * 256 +
                                 (koff ^ ((uint32_t)(d0 & 7) << 4));
            const uint32_t vb1 = sb + bufoff + 32768 + (uint32_t)(d0 + 1) * 256 +
                                 (koff ^ ((uint32_t)((d0 + 1) & 7) << 4));
            asm volatile("st.shared.b32 [%0], %1;" :: "r"(vb0),
                         "r"(__byte_perm(h0[dd], h1[dd], 0x5410)) : "memory");
            asm volatile("st.shared.b32 [%0], %1;" :: "r"(vb1),
                         "r"(__byte_perm(h0[dd], h1[dd], 0x7632)) : "memory");
        }
    }
    if (t < 128)
        reinterpret_cast<int*>(smem + ATT_MASK + slot * 512)[t] = bm[kv0 + t];
}

__global__ void __launch_bounds__(256, 1)
flash_attn_h(const hf* __restrict__ Q, const hf* __restrict__ K,
             const hf* __restrict__ V, const int* __restrict__ mask,
             hf* __restrict__ O) {
    extern __shared__ char smem[];
    const uint32_t sb = smem_to_u32(smem);
    const int t = threadIdx.x, lane = t & 31, w = t >> 5;
    const int qi = gridDim.x - 1 - blockIdx.x;
    const int h = blockIdx.y, b = blockIdx.z;
    const int q0 = qi * 128;
    const size_t base = (size_t)b * SEQ * D_MODEL + (size_t)h * HEAD_DIM;
    const int* bm = mask + b * SEQ;
    const float scale = 0.08838834764831845f;

    {
        const int row = t >> 1, half = t & 1;
        const uint4* gq = reinterpret_cast<const uint4*>(
            Q + base + (size_t)(q0 + row) * D_MODEL + half * 64);
        char* qr = smem + (uint32_t)row * 256;
        const uint32_t swr = ((uint32_t)(row & 7)) << 4;
        #pragma unroll
        for (int i = 0; i < 8; i++)
            *reinterpret_cast<uint4*>(
                qr + (((uint32_t)(half * 128 + i * 16)) ^ swr)) = gq[i];
    }
    att_stage(smem, sb, ATT_BUF0, K + base, V + base, bm, 0, 0, t);
    CPCOMMIT();
    CPWAIT(0);
    __syncthreads();

    uint32_t Aq[8][4];
    {
        const int r = w * 16 + (lane & 15);
        const uint32_t swz = ((uint32_t)(r & 7)) << 4;
        const uint32_t cgo = ((uint32_t)(lane >> 4)) << 4;
        const uint32_t qb = sb + (uint32_t)r * 256;
        #pragma unroll
        for (int ds = 0; ds < 8; ds++)
            ldsm_x4(qb + ((((uint32_t)(ds * 32)) + cgo) ^ swz), Aq[ds]);
    }
    __syncthreads();

    float m1 = -1e30f, l1 = 0.f, m2 = -1e30f, l2 = 0.f;
    float acc[16][4];
    #pragma unroll
    for (int nt = 0; nt < 16; nt++)
        #pragma unroll
        for (int c = 0; c < 4; c++) acc[nt][c] = 0.f;

    const int r1g = q0 + w * 16 + (lane >> 2);
    const int r2g = r1g + 8;
    const int nch = qi + 1;
    const uint32_t cgo = ((uint32_t)(lane >> 4)) << 4;

    for (int j = 0; j < nch; j++) {
        const int s = j & 1;
        const uint32_t bufo = s ? 0u : (uint32_t)ATT_BUF0;
        const int kv0 = j * 128;

        if (j + 1 < nch) {
            att_stage(smem, sb, s ? (uint32_t)ATT_BUF0 : 0u,
                      K + base, V + base, bm, kv0 + 128, (j + 1) & 1, t);
            CPCOMMIT();
        }

        float sacc[16][4];
        #pragma unroll
        for (int nt = 0; nt < 16; nt++)
            #pragma unroll
            for (int c = 0; c < 4; c++) sacc[nt][c] = 0.f;

        #pragma unroll
        for (int g4 = 0; g4 < 8; g4++) {
            const int kr = g4 * 16 + (lane & 15);
            const uint32_t swz = ((uint32_t)(kr & 7)) << 4;
            const uint32_t kb = sb + bufo + (uint32_t)kr * 256;
            #pragma unroll
            for (int ds = 0; ds < 8; ds++) {
                uint32_t r[4];
                ldsm_x4(kb + ((((uint32_t)(ds * 32)) + cgo) ^ swz), r);
                uint32_t b0[2] = {r[0], r[2]};
                uint32_t b1[2] = {r[1], r[3]};
                mma_f16(sacc[2 * g4 + 0], Aq[ds], b0);
                mma_f16(sacc[2 * g4 + 1], Aq[ds], b1);
            }
        }

        const int* mrow = reinterpret_cast<const int*>(smem + ATT_MASK + s * 512);
        #pragma unroll
        for (int nt = 0; nt < 16; nt++) {
            const int c0 = nt * 8 + (lane & 3) * 2;
            const int k0g = kv0 + c0, k1g = k0g + 1;
            const bool mv0 = mrow[c0] != 0, mv1 = mrow[c0 + 1] != 0;
            float v0 = sacc[nt][0] * scale, v1 = sacc[nt][1] * scale;
            float v2 = sacc[nt][2] * scale, v3 = sacc[nt][3] * scale;
            sacc[nt][0] = (k0g > r1g || !mv0) ? -1e9f : v0;
            sacc[nt][1] = (k1g > r1g || !mv1) ? -1e9f : v1;
            sacc[nt][2] = (k0g > r2g || !mv0) ? -1e9f : v2;
            sacc[nt][3] = (k1g > r2g || !mv1) ? -1e9f : v3;
        }

        float mx1 = -1e30f, mx2 = -1e30f;
        #pragma unroll
        for (int nt = 0; nt < 16; nt++) {
            mx1 = fmaxf(mx1, fmaxf(sacc[nt][0], sacc[nt][1]));
            mx2 = fmaxf(mx2, fmaxf(sacc[nt][2], sacc[nt][3]));
        }
        mx1 = fmaxf(mx1, __shfl_xor_sync(0xFFFFFFFFu, mx1, 1));
        mx1 = fmaxf(mx1, __shfl_xor_sync(0xFFFFFFFFu, mx1, 2));
        mx2 = fmaxf(mx2, __shfl_xor_sync(0xFFFFFFFFu, mx2, 1));
        mx2 = fmaxf(mx2, __shfl_xor_sync(0xFFFFFFFFu, mx2, 2));
        const float m1n = fmaxf(m1, mx1), m2n = fmaxf(m2, mx2);
        float s1 = 0.f, s2 = 0.f;
        #pragma unroll
        for (int nt = 0; nt < 16; nt++) {
            sacc[nt][0] = __expf(sacc[nt][0] - m1n);
            sacc[nt][1] = __expf(sacc[nt][1] - m1n);
            sacc[nt][2] = __expf(sacc[nt][2] - m2n);
            sacc[nt][3] = __expf(sacc[nt][3] - m2n);
            s1 += sacc[nt][0] + sacc[nt][1];
            s2 += sacc[nt][2] + sacc[nt][3];
        }
        s1 += __shfl_xor_sync(0xFFFFFFFFu, s1, 1);
        s1 += __shfl_xor_sync(0xFFFFFFFFu, s1, 2);
        s2 += __shfl_xor_sync(0xFFFFFFFFu, s2, 1);
        s2 += __shfl_xor_sync(0xFFFFFFFFu, s2, 2);
        if (j) {
            const float a1 = __expf(m1 - m1n), a2 = __expf(m2 - m2n);
            l1 = l1 * a1 + s1;
            l2 = l2 * a2 + s2;
            #pragma unroll
            for (int nt = 0; nt < 16; nt++) {
                acc[nt][0] *= a1; acc[nt][1] *= a1;
                acc[nt][2] *= a2; acc[nt][3] *= a2;
            }
        } else {
            l1 = s1;
            l2 = s2;
        }
        m1 = m1n;
        m2 = m2n;

        #pragma unroll
        for (int ks = 0; ks < 8; ks++) {
            const float* p0 = sacc[2 * ks];
            const float* p1 = sacc[2 * ks + 1];
            uint32_t pa[4];
            pa[0] = h2_bits(__floats2half2_rn(p0[0], p0[1]));
            pa[1] = h2_bits(__floats2half2_rn(p0[2], p0[3]));
            pa[2] = h2_bits(__floats2half2_rn(p1[0], p1[1]));
            pa[3] = h2_bits(__floats2half2_rn(p1[2], p1[3]));

            #pragma unroll
            for (int gd = 0; gd < 8; gd++) {
                const int dr = gd * 16 + (lane & 15);
                const uint32_t swz = ((uint32_t)(dr & 7)) << 4;
                const uint32_t vb = sb + bufo + 32768 + (uint32_t)dr * 256;
                uint32_t r[4];
                ldsm_x4(vb + ((((uint32_t)(ks * 32)) + cgo) ^ swz), r);
                uint32_t b0[2] = {r[0], r[2]};
                uint32_t b1[2] = {r[1], r[3]};
                mma_f16(acc[2 * gd + 0], pa, b0);
                mma_f16(acc[2 * gd + 1], pa, b1);
            }
        }

        CPWAIT(0);
        __syncthreads();
    }

    const float i1 = (l1 > 0.f) ? 1.f / l1 : 0.f;
    const float i2 = (l2 > 0.f) ? 1.f / l2 : 0.f;
    #pragma unroll
    for (int nt = 0; nt < 16; nt++) {
        const int col = nt * 8 + (lane & 3) * 2;
        *reinterpret_cast<uint32_t*>(O + base + (size_t)r1g * D_MODEL + col) =
            h2_bits(__floats2half2_rn(acc[nt][0] * i1, acc[nt][1] * i1));
        *reinterpret_cast<uint32_t*>(O + base + (size_t)r2g * D_MODEL + col) =
            h2_bits(__floats2half2_rn(acc[nt][2] * i2, acc[nt][3] * i2));
    }
}

// ---------------- launch -----------------------------------------------------
extern "C" void kernel_launch(void* const* d_in, const int* in_sizes, int n_in,
                              void* d_out, int out_size) {
    const float* x           = (const float*)d_in[0];
    const int*   attn_mask   = (const int*)  d_in[1];
    const float* w_norm_attn = (const float*)d_in[2];
    const float* wq          = (const float*)d_in[3];
    const float* wk          = (const float*)d_in[4];
    const float* wv          = (const float*)d_in[5];
    const float* wo          = (const float*)d_in[6];
    const float* w_norm_mlp  = (const float*)d_in[7];
    const float* w_up        = (const float*)d_in[8];
    const float* w_down      = (const float*)d_in[9];
    float* out = (float*)d_out;

    hf *h, *q, *k, *v, *att, *up;
    hf *rwq, *rwk, *rwv, *rwo, *rwu, *rwd;
    float* x1;
    cudaGetSymbolAddress((void**)&h, g_h);
    cudaGetSymbolAddress((void**)&q, g_q);
    cudaGetSymbolAddress((void**)&k, g_k);
    cudaGetSymbolAddress((void**)&v, g_v);
    cudaGetSymbolAddress((void**)&att, g_att);
    cudaGetSymbolAddress((void**)&up, g_up);
    cudaGetSymbolAddress((void**)&x1, g_x1);
    cudaGetSymbolAddress((void**)&rwq, g_wq);
    cudaGetSymbolAddress((void**)&rwk, g_wk);
    cudaGetSymbolAddress((void**)&rwv, g_wv);
    cudaGetSymbolAddress((void**)&rwo, g_wo);
    cudaGetSymbolAddress((void**)&rwu, g_wu);
    cudaGetSymbolAddress((void**)&rwd, g_wd);

    cudaFuncSetAttribute(flash_attn_h,
                         cudaFuncAttributeMaxDynamicSharedMemorySize, ATT_SMEM_BYTES);
    cudaFuncSetAttribute(qkv_gemm,
                         cudaFuncAttributeMaxDynamicSharedMemorySize, GEMM_SMEM);
    cudaFuncSetAttribute(mma_gemm<1>,
                         cudaFuncAttributeMaxDynamicSharedMemorySize, GEMM_SMEM);
    cudaFuncSetAttribute(mma_gemm<2>,
                         cudaFuncAttributeMaxDynamicSharedMemorySize, GEMM_SMEM);

    // 0) round weights to fp16 (once)
    const int DD4 = D_MODEL * D_MODEL / 4;
    const int UD4 = MLP_DIM * D_MODEL / 4;
    round_dd<<<dim3((DD4 + 255) / 256, 4), 256>>>(wq, wk, wv, wo,
                                                  rwq, rwk, rwv, rwo);
    round_ud<<<dim3((UD4 + 255) / 256, 2), 256>>>(w_up, w_down, rwu, rwd);

    // 1) rmsnorm(x) -> h (fp16), warp-per-row
    rmsnorm_h<<<TOK / 8, 256>>>(x, w_norm_attn, h);

    // 2) fused q,k,v projection
    dim3 gQKV(3 * D_MODEL / 256, TOK / 128);
    qkv_gemm<<<gQKV, GTHREADS, GEMM_SMEM>>>(h, rwq, rwk, rwv, q, k, v);

    // 3) attention (BKV=128)
    dim3 gA(SEQ / 128, N_HEADS, BATCH);
    flash_attn_h<<<gA, 256, ATT_SMEM_BYTES>>>(q, k, v, attn_mask, att);

    // 4) output projection + residual -> x1 (fp32)
    dim3 gD(D_MODEL / 256, TOK / 128);
    mma_gemm<2><<<gD, GTHREADS, GEMM_SMEM>>>(D_MODEL, D_MODEL,
                                             att, rwo, x, x1, nullptr);

    // 5) rmsnorm(x1) -> h, warp-per-row
    rmsnorm_h<<<TOK / 8, 256>>>(x1, w_norm_mlp, h);

    // 6) up projection + gelu (fp16 store)
    dim3 gU(MLP_DIM / 256, TOK / 128);
    mma_gemm<1><<<gU, GTHREADS, GEMM_SMEM>>>(MLP_DIM, D_MODEL,
                                             h, rwu, nullptr, nullptr, up);

    // 7) down projection + residual -> out (fp32)
    mma_gemm<2><<<gD, GTHREADS, GEMM_SMEM>>>(D_MODEL, MLP_DIM,
                                             up, rwd, x1, out, nullptr);
}

// round 17
// speedup vs baseline: 1.0237x; 1.0017x over previous
#include <cuda_runtime.h>
#include <cuda_fp16.h>
#include <math.h>
#include <stdint.h>

#define D_MODEL 2048
#define N_HEADS 16
#define HEAD_DIM 128
#define MLP_DIM 8192
#define BATCH 2
#define SEQ 2048
#define TOK (BATCH * SEQ)

typedef __half hf;

// ---------------- scratch (static device globals) ---------------------------
__device__ hf g_h[(size_t)TOK * D_MODEL];
__device__ hf g_q[(size_t)TOK * D_MODEL];
__device__ hf g_k[(size_t)TOK * D_MODEL];
__device__ hf g_v[(size_t)TOK * D_MODEL];
__device__ hf g_att[(size_t)TOK * D_MODEL];
__device__ hf g_up[(size_t)TOK * MLP_DIM];
__device__ float g_x1[(size_t)TOK * D_MODEL];
__device__ hf g_wq[(size_t)D_MODEL * D_MODEL];
__device__ hf g_wk[(size_t)D_MODEL * D_MODEL];
__device__ hf g_wv[(size_t)D_MODEL * D_MODEL];
__device__ hf g_wo[(size_t)D_MODEL * D_MODEL];
__device__ hf g_wu[(size_t)MLP_DIM * D_MODEL];
__device__ hf g_wd[(size_t)D_MODEL * MLP_DIM];

// ================= PTX helpers (baseline PTX, sm_80+) =======================
__device__ __forceinline__ uint32_t smem_to_u32(const void* p) {
    uint32_t a;
    asm("{ .reg .u64 t; cvta.to.shared.u64 t, %1; cvt.u32.u64 %0, t; }"
        : "=r"(a) : "l"(p));
    return a;
}
__device__ __forceinline__ void ldsm_x4(uint32_t addr, uint32_t* r) {
    asm volatile("ldmatrix.sync.aligned.m8n8.x4.shared.b16 {%0,%1,%2,%3}, [%4];"
                 : "=r"(r[0]), "=r"(r[1]), "=r"(r[2]), "=r"(r[3]) : "r"(addr));
}
__device__ __forceinline__ void mma_f16(float* d, const uint32_t* a,
                                        const uint32_t* b) {
    asm volatile(
        "mma.sync.aligned.m16n8k16.row.col.f32.f16.f16.f32 "
        "{%0,%1,%2,%3}, {%4,%5,%6,%7}, {%8,%9}, {%0,%1,%2,%3};"
        : "+f"(d[0]), "+f"(d[1]), "+f"(d[2]), "+f"(d[3])
        : "r"(a[0]), "r"(a[1]), "r"(a[2]), "r"(a[3]), "r"(b[0]), "r"(b[1]));
}
__device__ __forceinline__ uint32_t h2_bits(__half2 v) {
    return *reinterpret_cast<uint32_t*>(&v);
}
#define CP16(dst, src) \
    asm volatile("cp.async.cg.shared.global [%0], [%1], 16;" \
                 :: "r"(dst), "l"(src) : "memory")
#define CPCOMMIT() asm volatile("cp.async.commit_group;" ::: "memory")
#define CPWAIT(n)  asm volatile("cp.async.wait_group %0;" :: "n"(n) : "memory")

// fast exact-erf gelu (Abramowitz-Stegun 7.1.26, |eps|<=1.5e-7)
__device__ __forceinline__ float gelu_f(float x) {
    const float xs = x * 0.70710678118654752f;
    const float ax = fabsf(xs);
    const float t = __frcp_rn(fmaf(0.3275911f, ax, 1.0f));
    float poly = fmaf(1.061405429f, t, -1.453152027f);
    poly = fmaf(poly, t, 1.421413741f);
    poly = fmaf(poly, t, -0.284496736f);
    poly = fmaf(poly, t, 0.254829592f);
    const float e = __expf(-ax * ax);
    float erfv = 1.0f - poly * t * e;
    erfv = (xs < 0.f) ? -erfv : erfv;
    return 0.5f * x * (1.0f + erfv);
}

// ================= weight rounding fp32 -> fp16 (single launch) ==============
#define DD4 (D_MODEL * D_MODEL / 4)
#define UD4 (MLP_DIM * D_MODEL / 4)
#define DD_BLK (DD4 / 256)     // 4096
#define UD_BLK (UD4 / 256)     // 16384
#define ROUND_BLOCKS (4 * DD_BLK + 2 * UD_BLK)

__device__ __forceinline__ void round_store(const float* __restrict__ src,
                                            hf* __restrict__ dst, int i) {
    float4 v = reinterpret_cast<const float4*>(src)[i];
    __half2 a = __floats2half2_rn(v.x, v.y);
    __half2 b = __floats2half2_rn(v.z, v.w);
    reinterpret_cast<uint2*>(dst)[i] = make_uint2(h2_bits(a), h2_bits(b));
}
__global__ void round_all(const float* __restrict__ wq, const float* __restrict__ wk,
                          const float* __restrict__ wv, const float* __restrict__ wo,
                          const float* __restrict__ wu, const float* __restrict__ wd,
                          hf* oq, hf* ok, hf* ov, hf* oo, hf* ou, hf* od) {
    int bid = blockIdx.x;
    if (bid < 4 * DD_BLK) {
        int m = bid / DD_BLK;
        int i = (bid % DD_BLK) * 256 + threadIdx.x;
        switch (m) {
            case 0: round_store(wq, oq, i); break;
            case 1: round_store(wk, ok, i); break;
            case 2: round_store(wv, ov, i); break;
            default: round_store(wo, oo, i); break;
        }
        return;
    }
    bid -= 4 * DD_BLK;
    int m = bid / UD_BLK;
    int i = (bid % UD_BLK) * 256 + threadIdx.x;
    if (m == 0) round_store(wu, ou, i);
    else        round_store(wd, od, i);
}

// ================= RMSNorm -> fp16, one warp per row =========================
__global__ void __launch_bounds__(256)
rmsnorm_h(const float* __restrict__ x, const float* __restrict__ w,
          hf* __restrict__ out) {
    const int lane = threadIdx.x & 31;
    const int row = blockIdx.x * 8 + (threadIdx.x >> 5);
    const float4* xr = reinterpret_cast<const float4*>(x + (size_t)row * D_MODEL);
    const float4* w4 = reinterpret_cast<const float4*>(w);

    float4 v[16];
    float ss = 0.f;
    #pragma unroll
    for (int i = 0; i < 16; i++) {
        v[i] = xr[lane + i * 32];
        ss += v[i].x * v[i].x + v[i].y * v[i].y +
              v[i].z * v[i].z + v[i].w * v[i].w;
    }
    #pragma unroll
    for (int off = 16; off > 0; off >>= 1)
        ss += __shfl_xor_sync(0xFFFFFFFFu, ss, off);
    const float r = rsqrtf(ss / (float)D_MODEL + 1e-6f);

    uint2* o2 = reinterpret_cast<uint2*>(out + (size_t)row * D_MODEL);
    #pragma unroll
    for (int i = 0; i < 16; i++) {
        float4 ww = w4[lane + i * 32];
        __half2 a = __floats2half2_rn(v[i].x * r * ww.x, v[i].y * r * ww.y);
        __half2 b = __floats2half2_rn(v[i].z * r * ww.z, v[i].w * r * ww.w);
        o2[lane + i * 32] = make_uint2(h2_bits(a), h2_bits(b));
    }
}

// ================= FP16 GEMM (exact R11 config) ==============================
#define KC 64
#define ROWB 128
#define A_TILE 16384
#define B_TILE 32768
#define STAGE_B (A_TILE + B_TILE)
#define NSTAGE 4
#define GEMM_SMEM (NSTAGE * STAGE_B)   // 192 KB
#define GTHREADS 512

template <int EPI>
__device__ __forceinline__ void gemm_body(
    int Nc, int K, int m0, int c0,
    const hf* __restrict__ A, const hf* __restrict__ B,  // B pre-offset
    const float* __restrict__ RES, float* __restrict__ Cf,
    hf* __restrict__ Ch) {
    extern __shared__ char smem[];
    const uint32_t su = smem_to_u32(smem);

    const int t = threadIdx.x;
    const int lane = t & 31;
    const int wid = t >> 5;
    const int wm = wid & 3;
    const int wn = wid >> 2;

    const int arow = t >> 2;
    const int aseg = t & 3;
    const hf* Asrc = A + (size_t)(m0 + arow) * K + aseg * 16;
    const uint32_t asw = ((uint32_t)(arow & 7)) << 4;
    const uint32_t adst = (uint32_t)arow * ROWB;

    const int brow = t >> 1;
    const int bhalf = t & 1;
    const hf* Bsrc = B + (size_t)brow * K + bhalf * 32;
    const uint32_t bsw = ((uint32_t)(brow & 7)) << 4;
    const uint32_t bdst = (uint32_t)A_TILE + (uint32_t)brow * ROWB;

    auto CP_chunk = [&](int s, int k0) {
        const uint32_t st = su + (uint32_t)s * STAGE_B;
        #pragma unroll
        for (int c = 0; c < 2; c++)
            CP16(st + adst + (((uint32_t)(aseg * 32 + c * 16)) ^ asw),
                 Asrc + k0 + c * 8);
        #pragma unroll
        for (int c = 0; c < 4; c++)
            CP16(st + bdst + (((uint32_t)(bhalf * 64 + c * 16)) ^ bsw),
                 Bsrc + k0 + c * 8);
    };

    float acc[2][8][4];
    #pragma unroll
    for (int mt = 0; mt < 2; mt++)
        #pragma unroll
        for (int nt = 0; nt < 8; nt++)
            #pragma unroll
            for (int j = 0; j < 4; j++) acc[mt][nt][j] = 0.f;

    const int nch = K / KC;
    #pragma unroll
    for (int s = 0; s < NSTAGE - 1; s++) {
        CP_chunk(s, s * KC);
        CPCOMMIT();
    }

    const int lrow16 = lane & 15;
    const int cg = (lane >> 4) & 1;

    for (int i = 0; i < nch; i++) {
        CPWAIT(NSTAGE - 2);
        __syncthreads();

        const uint32_t st = su + (uint32_t)(i % NSTAGE) * STAGE_B;

        #pragma unroll
        for (int ks = 0; ks < 4; ks++) {
            const uint32_t cbh = (uint32_t)(ks * 32 + cg * 16);
            uint32_t Af[2][4];
            #pragma unroll
            for (int mt = 0; mt < 2; mt++) {
                const int row = wm * 32 + mt * 16 + lrow16;
                const uint32_t swz = (uint32_t)(row & 7) << 4;
                ldsm_x4(st + (uint32_t)row * ROWB + (cbh ^ swz), Af[mt]);
            }
            #pragma unroll
            for (int q = 0; q < 4; q++) {
                const int row = wn * 64 + q * 16 + lrow16;
                const uint32_t swz = (uint32_t)(row & 7) << 4;
                uint32_t r[4];
                ldsm_x4(st + A_TILE + (uint32_t)row * ROWB + (cbh ^ swz), r);
                uint32_t b0[2] = {r[0], r[2]};
                uint32_t b1[2] = {r[1], r[3]};
                #pragma unroll
                for (int mt = 0; mt < 2; mt++) {
                    mma_f16(acc[mt][2 * q + 0], Af[mt], b0);
                    mma_f16(acc[mt][2 * q + 1], Af[mt], b1);
                }
            }
        }

        if (i + NSTAGE - 1 < nch)
            CP_chunk((i + NSTAGE - 1) % NSTAGE, (i + NSTAGE - 1) * KC);
        CPCOMMIT();
    }

    const int er0 = m0 + wm * 32 + (lane >> 2);
    const int ec0 = c0 + wn * 64 + (lane & 3) * 2;
    #pragma unroll
    for (int mt = 0; mt < 2; mt++) {
        #pragma unroll
        for (int g = 0; g < 2; g++) {
            const int row = er0 + mt * 16 + g * 8;
            #pragma unroll
            for (int nt = 0; nt < 8; nt++) {
                const int col = ec0 + nt * 8;
                float v0 = acc[mt][nt][g * 2 + 0];
                float v1 = acc[mt][nt][g * 2 + 1];
                size_t roff = (size_t)row * Nc + col;
                if (EPI == 2) {
                    float2 r = *reinterpret_cast<const float2*>(RES + roff);
                    *reinterpret_cast<float2*>(Cf + roff) =
                        make_float2(v0 + r.x, v1 + r.y);
                } else {
                    if (EPI == 1) {
                        v0 = gelu_f(v0);
                        v1 = gelu_f(v1);
                    }
                    *reinterpret_cast<uint32_t*>(Ch + roff) =
                        h2_bits(__floats2half2_rn(v0, v1));
                }
            }
        }
    }
}

template <int EPI>
__global__ void __launch_bounds__(GTHREADS, 1)
mma_gemm(int N, int K,
         const hf* __restrict__ A, const hf* __restrict__ B,
         const float* __restrict__ RES, float* __restrict__ Cf,
         hf* __restrict__ Ch) {
    const int n0 = blockIdx.x * 256;
    gemm_body<EPI>(N, K, blockIdx.y * 128, n0, A, B + (size_t)n0 * K,
                   RES, Cf, Ch);
}

__global__ void __launch_bounds__(GTHREADS, 1)
qkv_gemm(const hf* __restrict__ h,
         const hf* __restrict__ wq, const hf* __restrict__ wk,
         const hf* __restrict__ wv,
         hf* __restrict__ q, hf* __restrict__ k, hf* __restrict__ v) {
    const int n0g = blockIdx.x * 256;
    const int sel = n0g >> 11;
    const int n0 = n0g & 2047;
    const hf* B;
    hf* C;
    if (sel == 0)      { B = wq; C = q; }
    else if (sel == 1) { B = wk; C = k; }
    else               { B = wv; C = v; }
    gemm_body<0>(D_MODEL, D_MODEL, blockIdx.y * 128, n0,
                 h, B + (size_t)n0 * D_MODEL, nullptr, nullptr, C);
}

// ================= FP16 flash attention, BKV=128 =============================
#define ATT_BUF0 65536
#define ATT_MASK 131072
#define ATT_SMEM_BYTES (131072 + 1024)

__device__ __forceinline__ void att_stage(
    char* smem, uint32_t sb, uint32_t bufoff,
    const hf* __restrict__ Kg, const hf* __restrict__ Vg,
    const int* __restrict__ bm, int kv0, int slot, int t) {
    {
        const int row = t >> 1;
        const int dq = (t & 1) * 64;
        const size_t goff = (size_t)(kv0 + row) * D_MODEL + dq;
        const uint32_t rbase = sb + bufoff + (uint32_t)row * 256;
        const uint32_t swr = ((uint32_t)(row & 7)) << 4;
        #pragma unroll
        for (int i = 0; i < 8; i++)
            CP16(rbase + (((uint32_t)(dq * 2 + i * 16)) ^ swr),
                 Kg + goff + i * 8);
    }
    {
        const int kvp = t & 63;
        const int dblk = t >> 6;
        const size_t r0 = (size_t)(kv0 + 2 * kvp) * D_MODEL + dblk * 32;
        const size_t r1 = r0 + D_MODEL;
        uint32_t h0[16], h1[16];
        #pragma unroll
        for (int c = 0; c < 4; c++) {
            uint4 a = *reinterpret_cast<const uint4*>(Vg + r0 + c * 8);
            uint4 b = *reinterpret_cast<const uint4*>(Vg + r1 + c * 8);
            h0[c * 4 + 0] = a.x; h0[c * 4 + 1] = a.y;
            h0[c * 4 + 2] = a.z; h0[c * 4 + 3] = a.w;
            h1[c * 4 + 0] = b.x; h1[c * 4 + 1] = b.y;
            h1[c * 4 + 2] = b.z; h1[c * 4 + 3] = b.w;
        }
        const uint32_t koff = (uint32_t)(kvp * 4);
        #pragma unroll
        for (int dd = 0; dd < 16; dd++) {
            const int d0 = dblk * 32 + dd * 2;
            const uint32_t vb0 = sb + bufoff + 32768 + (uint32_t)d0 * 256 +
                                 (koff ^ ((uint32_t)(d0 & 7) << 4));
            const uint32_t vb1 = sb + bufoff + 32768 + (uint32_t)(d0 + 1) * 256 +
                                 (koff ^ ((uint32_t)((d0 + 1) & 7) << 4));
            asm volatile("st.shared.b32 [%0], %1;" :: "r"(vb0),
                         "r"(__byte_perm(h0[dd], h1[dd], 0x5410)) : "memory");
            asm volatile("st.shared.b32 [%0], %1;" :: "r"(vb1),
                         "r"(__byte_perm(h0[dd], h1[dd], 0x7632)) : "memory");
        }
    }
    if (t < 128)
        reinterpret_cast<int*>(smem + ATT_MASK + slot * 512)[t] = bm[kv0 + t];
}

__global__ void __launch_bounds__(256, 1)
flash_attn_h(const hf* __restrict__ Q, const hf* __restrict__ K,
             const hf* __restrict__ V, const int* __restrict__ mask,
             hf* __restrict__ O) {
    extern __shared__ char smem[];
    const uint32_t sb = smem_to_u32(smem);
    const int t = threadIdx.x, lane = t & 31, w = t >> 5;
    const int qi = gridDim.x - 1 - blockIdx.x;
    const int h = blockIdx.y, b = blockIdx.z;
    const int q0 = qi * 128;
    const size_t base = (size_t)b * SEQ * D_MODEL + (size_t)h * HEAD_DIM;
    const int* bm = mask + b * SEQ;
    const float scale = 0.08838834764831845f;

    {
        const int row = t >> 1, half = t & 1;
        const uint4* gq = reinterpret_cast<const uint4*>(
            Q + base + (size_t)(q0 + row) * D_MODEL + half * 64);
        char* qr = smem + (uint32_t)row * 256;
        const uint32_t swr = ((uint32_t)(row & 7)) << 4;
        #pragma unroll
        for (int i = 0; i < 8; i++)
            *reinterpret_cast<uint4*>(
                qr + (((uint32_t)(half * 128 + i * 16)) ^ swr)) = gq[i];
    }
    att_stage(smem, sb, ATT_BUF0, K + base, V + base, bm, 0, 0, t);
    CPCOMMIT();
    CPWAIT(0);
    __syncthreads();

    uint32_t Aq[8][4];
    {
        const int r = w * 16 + (lane & 15);
        const uint32_t swz = ((uint32_t)(r & 7)) << 4;
        const uint32_t cgo = ((uint32_t)(lane >> 4)) << 4;
        const uint32_t qb = sb + (uint32_t)r * 256;
        #pragma unroll
        for (int ds = 0; ds < 8; ds++)
            ldsm_x4(qb + ((((uint32_t)(ds * 32)) + cgo) ^ swz), Aq[ds]);
    }
    __syncthreads();

    float m1 = -1e30f, l1 = 0.f, m2 = -1e30f, l2 = 0.f;
    float acc[16][4];
    #pragma unroll
    for (int nt = 0; nt < 16; nt++)
        #pragma unroll
        for (int c = 0; c < 4; c++) acc[nt][c] = 0.f;

    const int r1g = q0 + w * 16 + (lane >> 2);
    const int r2g = r1g + 8;
    const int nch = qi + 1;
    const uint32_t cgo = ((uint32_t)(lane >> 4)) << 4;

    for (int j = 0; j < nch; j++) {
        const int s = j & 1;
        const uint32_t bufo = s ? 0u : (uint32_t)ATT_BUF0;
        const int kv0 = j * 128;

        if (j + 1 < nch) {
            att_stage(smem, sb, s ? (uint32_t)ATT_BUF0 : 0u,
                      K + base, V + base, bm, kv0 + 128, (j + 1) & 1, t);
            CPCOMMIT();
        }

        float sacc[16][4];
        #pragma unroll
        for (int nt = 0; nt < 16; nt++)
            #pragma unroll
            for (int c = 0; c < 4; c++) sacc[nt][c] = 0.f;

        #pragma unroll
        for (int g4 = 0; g4 < 8; g4++) {
            const int kr = g4 * 16 + (lane & 15);
            const uint32_t swz = ((uint32_t)(kr & 7)) << 4;
            const uint32_t kb = sb + bufo + (uint32_t)kr * 256;
            #pragma unroll
            for (int ds = 0; ds < 8; ds++) {
                uint32_t r[4];
                ldsm_x4(kb + ((((uint32_t)(ds * 32)) + cgo) ^ swz), r);
                uint32_t b0[2] = {r[0], r[2]};
                uint32_t b1[2] = {r[1], r[3]};
                mma_f16(sacc[2 * g4 + 0], Aq[ds], b0);
                mma_f16(sacc[2 * g4 + 1], Aq[ds], b1);
            }
        }

        const int* mrow = reinterpret_cast<const int*>(smem + ATT_MASK + s * 512);
        #pragma unroll
        for (int nt = 0; nt < 16; nt++) {
            const int c0 = nt * 8 + (lane & 3) * 2;
            const int k0g = kv0 + c0, k1g = k0g + 1;
            const bool mv0 = mrow[c0] != 0, mv1 = mrow[c0 + 1] != 0;
            float v0 = sacc[nt][0] * scale, v1 = sacc[nt][1] * scale;
            float v2 = sacc[nt][2] * scale, v3 = sacc[nt][3] * scale;
            sacc[nt][0] = (k0g > r1g || !mv0) ? -1e9f : v0;
            sacc[nt][1] = (k1g > r1g || !mv1) ? -1e9f : v1;
            sacc[nt][2] = (k0g > r2g || !mv0) ? -1e9f : v2;
            sacc[nt][3] = (k1g > r2g || !mv1) ? -1e9f : v3;
        }

        float mx1 = -1e30f, mx2 = -1e30f;
        #pragma unroll
        for (int nt = 0; nt < 16; nt++) {
            mx1 = fmaxf(mx1, fmaxf(sacc[nt][0], sacc[nt][1]));
            mx2 = fmaxf(mx2, fmaxf(sacc[nt][2], sacc[nt][3]));
        }
        mx1 = fmaxf(mx1, __shfl_xor_sync(0xFFFFFFFFu, mx1, 1));
        mx1 = fmaxf(mx1, __shfl_xor_sync(0xFFFFFFFFu, mx1, 2));
        mx2 = fmaxf(mx2, __shfl_xor_sync(0xFFFFFFFFu, mx2, 1));
        mx2 = fmaxf(mx2, __shfl_xor_sync(0xFFFFFFFFu, mx2, 2));
        const float m1n = fmaxf(m1, mx1), m2n = fmaxf(m2, mx2);
        float s1 = 0.f, s2 = 0.f;
        #pragma unroll
        for (int nt = 0; nt < 16; nt++) {
            sacc[nt][0] = __expf(sacc[nt][0] - m1n);
            sacc[nt][1] = __expf(sacc[nt][1] - m1n);
            sacc[nt][2] = __expf(sacc[nt][2] - m2n);
            sacc[nt][3] = __expf(sacc[nt][3] - m2n);
            s1 += sacc[nt][0] + sacc[nt][1];
            s2 += sacc[nt][2] + sacc[nt][3];
        }
        s1 += __shfl_xor_sync(0xFFFFFFFFu, s1, 1);
        s1 += __shfl_xor_sync(0xFFFFFFFFu, s1, 2);
        s2 += __shfl_xor_sync(0xFFFFFFFFu, s2, 1);
        s2 += __shfl_xor_sync(0xFFFFFFFFu, s2, 2);
        if (j) {
            const float a1 = __expf(m1 - m1n), a2 = __expf(m2 - m2n);
            l1 = l1 * a1 + s1;
            l2 = l2 * a2 + s2;
            #pragma unroll
            for (int nt = 0; nt < 16; nt++) {
                acc[nt][0] *= a1; acc[nt][1] *= a1;
                acc[nt][2] *= a2; acc[nt][3] *= a2;
            }
        } else {
            l1 = s1;
            l2 = s2;
        }
        m1 = m1n;
        m2 = m2n;

        #pragma unroll
        for (int ks = 0; ks < 8; ks++) {
            const float* p0 = sacc[2 * ks];
            const float* p1 = sacc[2 * ks + 1];
            uint32_t pa[4];
            pa[0] = h2_bits(__floats2half2_rn(p0[0], p0[1]));
            pa[1] = h2_bits(__floats2half2_rn(p0[2], p0[3]));
            pa[2] = h2_bits(__floats2half2_rn(p1[0], p1[1]));
            pa[3] = h2_bits(__floats2half2_rn(p1[2], p1[3]));

            #pragma unroll
            for (int gd = 0; gd < 8; gd++) {
                const int dr = gd * 16 + (lane & 15);
                const uint32_t swz = ((uint32_t)(dr & 7)) << 4;
                const uint32_t vb = sb + bufo + 32768 + (uint32_t)dr * 256;
                uint32_t r[4];
                ldsm_x4(vb + ((((uint32_t)(ks * 32)) + cgo) ^ swz), r);
                uint32_t b0[2] = {r[0], r[2]};
                uint32_t b1[2] = {r[1], r[3]};
                mma_f16(acc[2 * gd + 0], pa, b0);
                mma_f16(acc[2 * gd + 1], pa, b1);
            }
        }

        CPWAIT(0);
        __syncthreads();
    }

    const float i1 = (l1 > 0.f) ? 1.f / l1 : 0.f;
    const float i2 = (l2 > 0.f) ? 1.f / l2 : 0.f;
    #pragma unroll
    for (int nt = 0; nt < 16; nt++) {
        const int col = nt * 8 + (lane & 3) * 2;
        *reinterpret_cast<uint32_t*>(O + base + (size_t)r1g * D_MODEL + col) =
            h2_bits(__floats2half2_rn(acc[nt][0] * i1, acc[nt][1] * i1));
        *reinterpret_cast<uint32_t*>(O + base + (size_t)r2g * D_MODEL + col) =
            h2_bits(__floats2half2_rn(acc[nt][2] * i2, acc[nt][3] * i2));
    }
}

// ---------------- launch -----------------------------------------------------
extern "C" void kernel_launch(void* const* d_in, const int* in_sizes, int n_in,
                              void* d_out, int out_size) {
    const float* x           = (const float*)d_in[0];
    const int*   attn_mask   = (const int*)  d_in[1];
    const float* w_norm_attn = (const float*)d_in[2];
    const float* wq          = (const float*)d_in[3];
    const float* wk          = (const float*)d_in[4];
    const float* wv          = (const float*)d_in[5];
    const float* wo          = (const float*)d_in[6];
    const float* w_norm_mlp  = (const float*)d_in[7];
    const float* w_up        = (const float*)d_in[8];
    const float* w_down      = (const float*)d_in[9];
    float* out = (float*)d_out;

    hf *h, *q, *k, *v, *att, *up;
    hf *rwq, *rwk, *rwv, *rwo, *rwu, *rwd;
    float* x1;
    cudaGetSymbolAddress((void**)&h, g_h);
    cudaGetSymbolAddress((void**)&q, g_q);
    cudaGetSymbolAddress((void**)&k, g_k);
    cudaGetSymbolAddress((void**)&v, g_v);
    cudaGetSymbolAddress((void**)&att, g_att);
    cudaGetSymbolAddress((void**)&up, g_up);
    cudaGetSymbolAddress((void**)&x1, g_x1);
    cudaGetSymbolAddress((void**)&rwq, g_wq);
    cudaGetSymbolAddress((void**)&rwk, g_wk);
    cudaGetSymbolAddress((void**)&rwv, g_wv);
    cudaGetSymbolAddress((void**)&rwo, g_wo);
    cudaGetSymbolAddress((void**)&rwu, g_wu);
    cudaGetSymbolAddress((void**)&rwd, g_wd);

    cudaFuncSetAttribute(flash_attn_h,
                         cudaFuncAttributeMaxDynamicSharedMemorySize, ATT_SMEM_BYTES);
    cudaFuncSetAttribute(qkv_gemm,
                         cudaFuncAttributeMaxDynamicSharedMemorySize, GEMM_SMEM);
    cudaFuncSetAttribute(mma_gemm<1>,
                         cudaFuncAttributeMaxDynamicSharedMemorySize, GEMM_SMEM);
    cudaFuncSetAttribute(mma_gemm<2>,
                         cudaFuncAttributeMaxDynamicSharedMemorySize, GEMM_SMEM);

    // 0) round all weights to fp16 (single launch)
    round_all<<<ROUND_BLOCKS, 256>>>(wq, wk, wv, wo, w_up, w_down,
                                     rwq, rwk, rwv, rwo, rwu, rwd);

    // 1) rmsnorm(x) -> h (fp16), warp-per-row
    rmsnorm_h<<<TOK / 8, 256>>>(x, w_norm_attn, h);

    // 2) fused q,k,v projection
    dim3 gQKV(3 * D_MODEL / 256, TOK / 128);
    qkv_gemm<<<gQKV, GTHREADS, GEMM_SMEM>>>(h, rwq, rwk, rwv, q, k, v);

    // 3) attention (BKV=128)
    dim3 gA(SEQ / 128, N_HEADS, BATCH);
    flash_attn_h<<<gA, 256, ATT_SMEM_BYTES>>>(q, k, v, attn_mask, att);

    // 4) output projection + residual -> x1 (fp32)
    dim3 gD(D_MODEL / 256, TOK / 128);
    mma_gemm<2><<<gD, GTHREADS, GEMM_SMEM>>>(D_MODEL, D_MODEL,
                                             att, rwo, x, x1, nullptr);

    // 5) rmsnorm(x1) -> h, warp-per-row
    rmsnorm_h<<<TOK / 8, 256>>>(x1, w_norm_mlp, h);

    // 6) up projection + gelu (fp16 store)
    dim3 gU(MLP_DIM / 256, TOK / 128);
    mma_gemm<1><<<gU, GTHREADS, GEMM_SMEM>>>(MLP_DIM, D_MODEL,
                                             h, rwu, nullptr, nullptr, up);

    // 7) down projection + residual -> out (fp32)
    mma_gemm<2><<<gD, GTHREADS, GEMM_SMEM>>>(D_MODEL, MLP_DIM,
                                             up, rwd, x1, out, nullptr);
}